// round 14
// baseline (speedup 1.0000x reference)
#include <cuda_runtime.h>
#include <math.h>
#include <stdint.h>

// Problem constants: B=64, S=2048, I=256, H=256, G=2H=512
#define BATCH 64
#define SEQ   2048
#define HID   256
#define GATES 512
#define WROWS 272          // rows in global transposed weights (>=256 zero)
#define ZROW  256          // all-zero row index (sentinel)

// -------- scratch (static device arrays; no allocation) --------
__device__ float g_gx[67108864];          // (B*S, 512) fp32 = 256 MB
__device__ float g_WhT0[WROWS * GATES];   // [j][g]
__device__ float g_WiT1[WROWS * GATES];
__device__ float g_WhT1[WROWS * GATES];

// ---------------------------------------------------------------
// Kernel 0: transpose weights into padded [j][g] layout; zero pad rows.
// ---------------------------------------------------------------
__global__ void prep_kernel(const float* __restrict__ Wh0,
                            const float* __restrict__ Wi1,
                            const float* __restrict__ Wh1)
{
    int idx = blockIdx.x * 256 + threadIdx.x;
    const int perp = WROWS * GATES;
    if (idx < 3 * perp) {
        int m = idx / perp;
        int e = idx - m * perp;
        int j = e >> 9;
        int g = e & 511;
        const float* src = (m == 0) ? Wh0 : (m == 1) ? Wi1 : Wh1;
        float*       dst = (m == 0) ? g_WhT0 : (m == 1) ? g_WiT1 : g_WhT1;
        dst[e] = (j < HID) ? src[g * HID + j] : 0.0f;
    }
}

// ---------------------------------------------------------------
// Kernel 1: gx0 = (x @ Wi0^T + bi0) + bh0   (unchanged — passing)
// ---------------------------------------------------------------
__global__ void __launch_bounds__(256, 2)
gemm_gx_kernel(const float* __restrict__ x,
               const float* __restrict__ Wi0,
               const float* __restrict__ bi0,
               const float* __restrict__ bh0)
{
    __shared__ float As[32][68];
    __shared__ float Bs[32][68];

    const int m0  = blockIdx.x * 64;
    const int n0  = blockIdx.y * 64;
    const int tid = threadIdx.x;
    const int tx  = tid & 15;
    const int ty  = tid >> 4;

    float acc[4][4];
#pragma unroll
    for (int i = 0; i < 4; i++)
#pragma unroll
        for (int j = 0; j < 4; j++) acc[i][j] = 0.f;

    for (int k0 = 0; k0 < 256; k0 += 32) {
#pragma unroll
        for (int v = 0; v < 2; v++) {
            int idx = tid + v * 256;
            int r   = idx >> 3;
            int kk  = (idx & 7) << 2;
            float4 av = *reinterpret_cast<const float4*>(
                x + (size_t)(m0 + r) * 256 + (k0 + kk));
            As[kk + 0][r] = av.x; As[kk + 1][r] = av.y;
            As[kk + 2][r] = av.z; As[kk + 3][r] = av.w;
            float4 bv = *reinterpret_cast<const float4*>(
                Wi0 + (size_t)(n0 + r) * 256 + (k0 + kk));
            Bs[kk + 0][r] = bv.x; Bs[kk + 1][r] = bv.y;
            Bs[kk + 2][r] = bv.z; Bs[kk + 3][r] = bv.w;
        }
        __syncthreads();
#pragma unroll
        for (int k = 0; k < 32; k++) {
            float4 av = *reinterpret_cast<const float4*>(&As[k][ty << 2]);
            float4 bv = *reinterpret_cast<const float4*>(&Bs[k][tx << 2]);
            float aa[4] = {av.x, av.y, av.z, av.w};
            float bb[4] = {bv.x, bv.y, bv.z, bv.w};
#pragma unroll
            for (int i = 0; i < 4; i++)
#pragma unroll
                for (int j = 0; j < 4; j++)
                    acc[i][j] = __fmaf_rn(aa[i], bb[j], acc[i][j]);
        }
        __syncthreads();
    }

    float4 b1 = *reinterpret_cast<const float4*>(bi0 + n0 + (tx << 2));
    float4 b2 = *reinterpret_cast<const float4*>(bh0 + n0 + (tx << 2));

#pragma unroll
    for (int i = 0; i < 4; i++) {
        int r = m0 + (ty << 2) + i;
        float4 o;
        o.x = __fadd_rn(__fadd_rn(acc[i][0], b1.x), b2.x);
        o.y = __fadd_rn(__fadd_rn(acc[i][1], b1.y), b2.y);
        o.z = __fadd_rn(__fadd_rn(acc[i][2], b1.z), b2.z);
        o.w = __fadd_rn(__fadd_rn(acc[i][3], b1.w), b2.w);
        *reinterpret_cast<float4*>(g_gx + (size_t)r * GATES + n0 + (tx << 2)) = o;
    }
}

// ---------------------------------------------------------------
// Cluster helpers (4-CTA clusters)
// ---------------------------------------------------------------
__device__ __forceinline__ unsigned ctarank()
{
    unsigned r;
    asm("mov.u32 %0, %%cluster_ctarank;" : "=r"(r));
    return r;
}

#define CLUSTER_SYNC() do {                                            \
    asm volatile("barrier.cluster.arrive.aligned;" ::: "memory");      \
    asm volatile("barrier.cluster.wait.aligned;"   ::: "memory");      \
} while (0)

__device__ __forceinline__ void remote_st_u32(void* lptr, int rank, unsigned val)
{
    unsigned laddr;
    asm("{ .reg .u64 t; cvta.to.shared.u64 t, %1; cvt.u32.u64 %0, t; }"
        : "=r"(laddr) : "l"(lptr));
    unsigned raddr;
    asm volatile("mapa.shared::cluster.u32 %0, %1, %2;"
                 : "=r"(raddr) : "r"(laddr), "r"(rank));
    asm volatile("st.shared::cluster.u32 [%0], %1;"
                 :: "r"(raddr), "r"(val) : "memory");
}

// XLA logistic: 1/(1+exp(-x)), exp via fp64 rounded to f32 (passing numerics).
__device__ __forceinline__ float sigmoid_ref(float g)
{
    float ef = (float)exp(-(double)g);
    return __fdiv_rn(1.0f, __fadd_rn(1.0f, ef));
}

// ---------------------------------------------------------------
// float2 active-row sum (bit-exact since R7): two independent
// single-accumulator chains in strictly ascending j order; ZROW pads
// add exact +0.0f. 16 independent LDG.64 per batch -> MLP=16/thread.
// ---------------------------------------------------------------
__device__ __forceinline__ float2 mv2(const float* __restrict__ Wb,
                                      const int* __restrict__ lst, int n16)
{
    float2 m = make_float2(0.f, 0.f);
    const int4* l4 = reinterpret_cast<const int4*>(lst);
    const int nb = n16 >> 4;
    for (int k = 0; k < nb; k++) {
        int4 a = l4[k * 4 + 0];
        int4 b = l4[k * 4 + 1];
        int4 c = l4[k * 4 + 2];
        int4 d = l4[k * 4 + 3];
        float2 w0  = *reinterpret_cast<const float2*>(Wb + ((size_t)a.x << 9));
        float2 w1  = *reinterpret_cast<const float2*>(Wb + ((size_t)a.y << 9));
        float2 w2  = *reinterpret_cast<const float2*>(Wb + ((size_t)a.z << 9));
        float2 w3  = *reinterpret_cast<const float2*>(Wb + ((size_t)a.w << 9));
        float2 w4  = *reinterpret_cast<const float2*>(Wb + ((size_t)b.x << 9));
        float2 w5  = *reinterpret_cast<const float2*>(Wb + ((size_t)b.y << 9));
        float2 w6  = *reinterpret_cast<const float2*>(Wb + ((size_t)b.z << 9));
        float2 w7  = *reinterpret_cast<const float2*>(Wb + ((size_t)b.w << 9));
        float2 w8  = *reinterpret_cast<const float2*>(Wb + ((size_t)c.x << 9));
        float2 w9  = *reinterpret_cast<const float2*>(Wb + ((size_t)c.y << 9));
        float2 w10 = *reinterpret_cast<const float2*>(Wb + ((size_t)c.z << 9));
        float2 w11 = *reinterpret_cast<const float2*>(Wb + ((size_t)c.w << 9));
        float2 w12 = *reinterpret_cast<const float2*>(Wb + ((size_t)d.x << 9));
        float2 w13 = *reinterpret_cast<const float2*>(Wb + ((size_t)d.y << 9));
        float2 w14 = *reinterpret_cast<const float2*>(Wb + ((size_t)d.z << 9));
        float2 w15 = *reinterpret_cast<const float2*>(Wb + ((size_t)d.w << 9));
        m.x = __fadd_rn(m.x, w0.x);  m.y = __fadd_rn(m.y, w0.y);
        m.x = __fadd_rn(m.x, w1.x);  m.y = __fadd_rn(m.y, w1.y);
        m.x = __fadd_rn(m.x, w2.x);  m.y = __fadd_rn(m.y, w2.y);
        m.x = __fadd_rn(m.x, w3.x);  m.y = __fadd_rn(m.y, w3.y);
        m.x = __fadd_rn(m.x, w4.x);  m.y = __fadd_rn(m.y, w4.y);
        m.x = __fadd_rn(m.x, w5.x);  m.y = __fadd_rn(m.y, w5.y);
        m.x = __fadd_rn(m.x, w6.x);  m.y = __fadd_rn(m.y, w6.y);
        m.x = __fadd_rn(m.x, w7.x);  m.y = __fadd_rn(m.y, w7.y);
        m.x = __fadd_rn(m.x, w8.x);  m.y = __fadd_rn(m.y, w8.y);
        m.x = __fadd_rn(m.x, w9.x);  m.y = __fadd_rn(m.y, w9.y);
        m.x = __fadd_rn(m.x, w10.x); m.y = __fadd_rn(m.y, w10.y);
        m.x = __fadd_rn(m.x, w11.x); m.y = __fadd_rn(m.y, w11.y);
        m.x = __fadd_rn(m.x, w12.x); m.y = __fadd_rn(m.y, w12.y);
        m.x = __fadd_rn(m.x, w13.x); m.y = __fadd_rn(m.y, w13.y);
        m.x = __fadd_rn(m.x, w14.x); m.y = __fadd_rn(m.y, w14.y);
        m.x = __fadd_rn(m.x, w15.x); m.y = __fadd_rn(m.y, w15.y);
    }
    return m;
}

// pair index k in [0,64) -> global gate col of pair base 2k for CTA rank r.
// CTA owns units [64r,64r+64): f cols 64r+0..63, c cols 256+64r+0..63.
__device__ __forceinline__ int paircol4(int k, int rank)
{
    int c = 2 * k;
    return (c < 64) ? (64 * rank + c) : (256 + 64 * rank + (c - 64));
}

// ---------------------------------------------------------------
// Kernel 2: spiking-LSTM scan, depth-2 pipelined. 32 clusters x 4 CTAs.
// Cluster handles 2 batch elements; CTA rank r owns units [64r,64r+64)
// -> per-CTA weight footprint 384 KB (high L1 hit). ONE cluster sync/step.
//   update phase: tid 0-127: L0(t) q=tid>>6 | tid 128-255: L1(t-1)
//   [cluster sync; build lst0(t) x2 and lst1(t-1) x2]
//   matvec phase: 6 roles x 64 thr: Wi1/Wh0/Wh1 for q=0,1 | tid>=384: gx
// ---------------------------------------------------------------
__global__ void __launch_bounds__(512, 1) __cluster_dims__(4, 1, 1)
recurrent4(const float* __restrict__ bi1,
           const float* __restrict__ bh1,
           float* __restrict__ out)
{
    const int tid  = threadIdx.x;
    const int lane = tid & 31;
    const int warp = tid >> 5;
    const int rank = (int)ctarank();
    const int b0   = (blockIdx.x >> 2) * 2;     // first batch of this cluster

    __shared__ float gxs[1024];    // [2 buf][2 q][128: 64 f + 64 c]
    __shared__ float m0s[256];     // [q][128] Wh0 . h0(t-1)
    __shared__ float mhs[256];     // [q][128] Wh1 . h1(t-2->t-1)
    __shared__ float g1s[256];     // [q][128] (Wi1.h0 + bi1) + bh1
    __shared__ float c0s[128], c1s[128];        // [q][64]
    __shared__ alignas(16) int lst0[2][WROWS], lst1[2][WROWS];
    __shared__ unsigned msk0[2][8], msk1[2][8];
    __shared__ int n0s[2], n1s[2];

    if (tid < 256) { m0s[tid] = 0.f; mhs[tid] = 0.f; g1s[tid] = 0.f; }
    if (tid < 128) { c0s[tid] = 0.f; c1s[tid] = 0.f; }
    if (tid < 16)  { msk0[tid >> 3][tid & 7] = 0u; msk1[tid >> 3][tid & 7] = 0u; }
    if (tid < 4)   { n0s[tid & 1] = 0; n1s[tid & 1] = 0; }
    if (tid < WROWS) {
        lst0[0][tid] = ZROW; lst0[1][tid] = ZROW;
        lst1[0][tid] = ZROW; lst1[1][tid] = ZROW;
    }

    // biases for the two Wi1 roles (tid<128): k = tid&63
    float2 bi1v = make_float2(0.f, 0.f), bh1v = bi1v;
    if (tid < 128) {
        int g0 = paircol4(tid & 63, rank);
        bi1v = *reinterpret_cast<const float2*>(bi1 + g0);
        bh1v = *reinterpret_cast<const float2*>(bh1 + g0);
    }

    const int ubase = rank * 64;

    // prefetch gx(0) into buffer 0
    if (tid >= 384) {
        int v = tid - 384;            // 0..127
        int q = v >> 6, i = v & 63;
        const float* gq = g_gx + (size_t)(b0 + q) * ((size_t)SEQ * GATES);
        gxs[q * 128 + i]      = __ldcg(gq + (ubase + i));
        gxs[q * 128 + 64 + i] = __ldcg(gq + (256 + ubase + i));
    }
    __syncthreads();

    for (int t = 0; t < SEQ; ++t) {
        const int pb = (t & 1) * 512;

        // ---------------- update phase ----------------
        if (tid < 128) {
            // L0(t) for batch q, unit u
            int q = tid >> 6, u = tid & 63;
            float g  = __fadd_rn(gxs[pb + q * 128 + u],      m0s[q * 128 + u]);
            float ct = __fadd_rn(gxs[pb + q * 128 + 64 + u], m0s[q * 128 + 64 + u]);
            float f  = sigmoid_ref(g);
            float cc = __fadd_rn(__fmul_rn(f, c0s[q * 64 + u]),
                                 __fmul_rn(__fsub_rn(1.0f, f), ct));
            c0s[q * 64 + u] = cc;
            unsigned bal = __ballot_sync(0xffffffffu, cc > 0.f);
            if (lane == 0) {
                int q2 = warp >> 1, half = warp & 1;
#pragma unroll
                for (int p = 0; p < 4; p++)
                    remote_st_u32(&msk0[q2][2 * rank + half], p, bal);
            }
        } else if (tid < 256 && t > 0) {
            // L1(t-1) for batch q, unit u
            int v = tid - 128;
            int q = v >> 6, u = v & 63;
            float g  = __fadd_rn(g1s[q * 128 + u],      mhs[q * 128 + u]);
            float ct = __fadd_rn(g1s[q * 128 + 64 + u], mhs[q * 128 + 64 + u]);
            float f  = sigmoid_ref(g);
            float cc = __fadd_rn(__fmul_rn(f, c1s[q * 64 + u]),
                                 __fmul_rn(__fsub_rn(1.0f, f), ct));
            c1s[q * 64 + u] = cc;
            float h = (cc > 0.f) ? 1.f : 0.f;
            out[((size_t)(b0 + q) * SEQ + (t - 1)) * HID + (ubase + u)] = h;
            unsigned bal = __ballot_sync(0xffffffffu, cc > 0.f);
            if (lane == 0) {
                int w4 = warp - 4;
                int q2 = w4 >> 1, half = w4 & 1;
#pragma unroll
                for (int p = 0; p < 4; p++)
                    remote_st_u32(&msk1[q2][2 * rank + half], p, bal);
            }
        }
        CLUSTER_SYNC();                        // all masks visible

        // ---- builds: lst0(t) q=0,1 and lst1(t-1) q=0,1 (ascending) ----
#pragma unroll
        for (int part = 0; part < 2; part++) {
            int idx = tid + part * 512;        // 0..1023
            int lid = idx >> 8;                // 0..3
            int j   = idx & 255;
            const unsigned* MM = (lid < 2) ? msk0[lid] : msk1[lid - 2];
            int* L = (lid < 2) ? lst0[lid] : lst1[lid - 2];
            int pre = 0, tot = 0;
            unsigned mw = 0;
#pragma unroll
            for (int w = 0; w < 8; w++) {
                unsigned mm = MM[w];
                tot += __popc(mm);
                if (w < (j >> 5)) pre += __popc(mm);
                else if (w == (j >> 5)) {
                    mw = mm;
                    pre += __popc(mm & ((1u << (j & 31)) - 1u));
                }
            }
            if ((mw >> (j & 31)) & 1u) L[pre] = j;
            if (j < 16) L[tot + j] = ZROW;
            if (j == 0) {
                int n16 = (tot + 15) & ~15;
                if (lid < 2) n0s[lid] = n16; else n1s[lid - 2] = n16;
            }
        }
        __syncthreads();

        // ---------------- matvec phase (6 roles concurrent) ----------
        {
            int role = tid >> 6;               // 0..7
            int k    = tid & 63;
            if (role < 2) {
                // Wi1 . h0(t), batch q=role
                int q = role;
                int g0 = paircol4(k, rank);
                float2 mi = mv2(g_WiT1 + g0, lst0[q], n0s[q]);
                float2 gi;
                gi.x = __fadd_rn(__fadd_rn(mi.x, bi1v.x), bh1v.x);
                gi.y = __fadd_rn(__fadd_rn(mi.y, bi1v.y), bh1v.y);
                *reinterpret_cast<float2*>(&g1s[q * 128 + 2 * k]) = gi;
            } else if (role < 4) {
                // Wh0 . h0(t), batch q=role-2  (for next step's L0)
                int q = role - 2;
                int g0 = paircol4(k, rank);
                float2 m0 = mv2(g_WhT0 + g0, lst0[q], n0s[q]);
                *reinterpret_cast<float2*>(&m0s[q * 128 + 2 * k]) = m0;
            } else if (role < 6) {
                // Wh1 . h1(t-1), batch q=role-4
                int q = role - 4;
                int g0 = paircol4(k, rank);
                float2 mh = mv2(g_WhT1 + g0, lst1[q], n1s[q]);
                *reinterpret_cast<float2*>(&mhs[q * 128 + 2 * k]) = mh;
            } else {
                // gx prefetch for t+1
                int tn = t + 1;
                if (tn < SEQ) {
                    int v = tid - 384;         // 0..127
                    int q = v >> 6, i = v & 63;
                    int nb = (tn & 1) * 512;
                    const float* gq = g_gx + (size_t)(b0 + q) * ((size_t)SEQ * GATES)
                                    + (size_t)tn * GATES;
                    gxs[nb + q * 128 + i]      = __ldcg(gq + (ubase + i));
                    gxs[nb + q * 128 + 64 + i] = __ldcg(gq + (256 + ubase + i));
                }
            }
        }
        __syncthreads();
    }

    // -------- epilogue: L1 update for step SEQ-1 --------
    if (tid < 128) {
        int q = tid >> 6, u = tid & 63;
        float g  = __fadd_rn(g1s[q * 128 + u],      mhs[q * 128 + u]);
        float ct = __fadd_rn(g1s[q * 128 + 64 + u], mhs[q * 128 + 64 + u]);
        float f  = sigmoid_ref(g);
        float cc = __fadd_rn(__fmul_rn(f, c1s[q * 64 + u]),
                             __fmul_rn(__fsub_rn(1.0f, f), ct));
        c1s[q * 64 + u] = cc;
        out[((size_t)(b0 + q) * SEQ + (SEQ - 1)) * HID + (ubase + u)] =
            (cc > 0.f) ? 1.f : 0.f;
    }
    __syncthreads();

    // finals: h_n (2,B,H) then c_n (2,B,H) after the (B,S,H) output
    if (tid < 128) {
        int q = tid >> 6, u = tid & 63;
        const size_t HN = (size_t)BATCH * SEQ * HID;
        const size_t CN = HN + (size_t)2 * BATCH * HID;
        const int bb = b0 + q;
        const int ui = ubase + u;
        float cc0 = c0s[q * 64 + u], cc1 = c1s[q * 64 + u];
        out[HN + ((size_t)0 * BATCH + bb) * HID + ui] = (cc0 > 0.f) ? 1.f : 0.f;
        out[HN + ((size_t)1 * BATCH + bb) * HID + ui] = (cc1 > 0.f) ? 1.f : 0.f;
        out[CN + ((size_t)0 * BATCH + bb) * HID + ui] = cc0;
        out[CN + ((size_t)1 * BATCH + bb) * HID + ui] = cc1;
    }
}

// ---------------------------------------------------------------
extern "C" void kernel_launch(void* const* d_in, const int* in_sizes, int n_in,
                              void* d_out, int out_size)
{
    const float* x   = (const float*)d_in[0];
    const float* Wi0 = (const float*)d_in[1];
    const float* bi0 = (const float*)d_in[2];
    const float* Wh0 = (const float*)d_in[3];
    const float* bh0 = (const float*)d_in[4];
    const float* Wi1 = (const float*)d_in[5];
    const float* bi1 = (const float*)d_in[6];
    const float* Wh1 = (const float*)d_in[7];
    const float* bh1 = (const float*)d_in[8];
    float* out = (float*)d_out;

    prep_kernel<<<1632, 256>>>(Wh0, Wi1, Wh1);

    dim3 gg(2048, 8);
    gemm_gx_kernel<<<gg, 256>>>(x, Wi0, bi0, bh0);

    // 32 clusters x 4 CTAs = 128 CTAs; cluster handles 2 batch elements
    recurrent4<<<BATCH / 2 * 4, 512>>>(bi1, bh1, out);
}

// round 15
// speedup vs baseline: 1.0872x; 1.0872x over previous
#include <cuda_runtime.h>
#include <math.h>
#include <stdint.h>

// Problem constants: B=64, S=2048, I=256, H=256, G=2H=512
#define BATCH 64
#define SEQ   2048
#define HID   256
#define GATES 512
#define WROWS 272          // rows in global transposed weights (>=256 zero)
#define ZROW  256          // all-zero row index (sentinel)

// -------- scratch (static device arrays; no allocation) --------
__device__ float g_gx[67108864];          // (B*S, 512) fp32 = 256 MB
__device__ float g_WhT0[WROWS * GATES];   // [j][g]
__device__ float g_WiT1[WROWS * GATES];
__device__ float g_WhT1[WROWS * GATES];

// ---------------------------------------------------------------
// Kernel 0: transpose weights into padded [j][g] layout; zero pad rows.
// ---------------------------------------------------------------
__global__ void prep_kernel(const float* __restrict__ Wh0,
                            const float* __restrict__ Wi1,
                            const float* __restrict__ Wh1)
{
    int idx = blockIdx.x * 256 + threadIdx.x;
    const int perp = WROWS * GATES;
    if (idx < 3 * perp) {
        int m = idx / perp;
        int e = idx - m * perp;
        int j = e >> 9;
        int g = e & 511;
        const float* src = (m == 0) ? Wh0 : (m == 1) ? Wi1 : Wh1;
        float*       dst = (m == 0) ? g_WhT0 : (m == 1) ? g_WiT1 : g_WhT1;
        dst[e] = (j < HID) ? src[g * HID + j] : 0.0f;
    }
}

// ---------------------------------------------------------------
// Kernel 1: gx0 = (x @ Wi0^T + bi0) + bh0   (unchanged — passing)
// ---------------------------------------------------------------
__global__ void __launch_bounds__(256, 2)
gemm_gx_kernel(const float* __restrict__ x,
               const float* __restrict__ Wi0,
               const float* __restrict__ bi0,
               const float* __restrict__ bh0)
{
    __shared__ float As[32][68];
    __shared__ float Bs[32][68];

    const int m0  = blockIdx.x * 64;
    const int n0  = blockIdx.y * 64;
    const int tid = threadIdx.x;
    const int tx  = tid & 15;
    const int ty  = tid >> 4;

    float acc[4][4];
#pragma unroll
    for (int i = 0; i < 4; i++)
#pragma unroll
        for (int j = 0; j < 4; j++) acc[i][j] = 0.f;

    for (int k0 = 0; k0 < 256; k0 += 32) {
#pragma unroll
        for (int v = 0; v < 2; v++) {
            int idx = tid + v * 256;
            int r   = idx >> 3;
            int kk  = (idx & 7) << 2;
            float4 av = *reinterpret_cast<const float4*>(
                x + (size_t)(m0 + r) * 256 + (k0 + kk));
            As[kk + 0][r] = av.x; As[kk + 1][r] = av.y;
            As[kk + 2][r] = av.z; As[kk + 3][r] = av.w;
            float4 bv = *reinterpret_cast<const float4*>(
                Wi0 + (size_t)(n0 + r) * 256 + (k0 + kk));
            Bs[kk + 0][r] = bv.x; Bs[kk + 1][r] = bv.y;
            Bs[kk + 2][r] = bv.z; Bs[kk + 3][r] = bv.w;
        }
        __syncthreads();
#pragma unroll
        for (int k = 0; k < 32; k++) {
            float4 av = *reinterpret_cast<const float4*>(&As[k][ty << 2]);
            float4 bv = *reinterpret_cast<const float4*>(&Bs[k][tx << 2]);
            float aa[4] = {av.x, av.y, av.z, av.w};
            float bb[4] = {bv.x, bv.y, bv.z, bv.w};
#pragma unroll
            for (int i = 0; i < 4; i++)
#pragma unroll
                for (int j = 0; j < 4; j++)
                    acc[i][j] = __fmaf_rn(aa[i], bb[j], acc[i][j]);
        }
        __syncthreads();
    }

    float4 b1 = *reinterpret_cast<const float4*>(bi0 + n0 + (tx << 2));
    float4 b2 = *reinterpret_cast<const float4*>(bh0 + n0 + (tx << 2));

#pragma unroll
    for (int i = 0; i < 4; i++) {
        int r = m0 + (ty << 2) + i;
        float4 o;
        o.x = __fadd_rn(__fadd_rn(acc[i][0], b1.x), b2.x);
        o.y = __fadd_rn(__fadd_rn(acc[i][1], b1.y), b2.y);
        o.z = __fadd_rn(__fadd_rn(acc[i][2], b1.z), b2.z);
        o.w = __fadd_rn(__fadd_rn(acc[i][3], b1.w), b2.w);
        *reinterpret_cast<float4*>(g_gx + (size_t)r * GATES + n0 + (tx << 2)) = o;
    }
}

// ---------------------------------------------------------------
// Cluster helpers (2-CTA clusters)
// ---------------------------------------------------------------
__device__ __forceinline__ unsigned ctarank()
{
    unsigned r;
    asm("mov.u32 %0, %%cluster_ctarank;" : "=r"(r));
    return r;
}

// Used ONLY at startup (init ordering) and shutdown (exit safety).
// NOT in the per-step loop: barrier.cluster emits CCTL.IVALL (L1D flush).
#define CLUSTER_SYNC() do {                                            \
    asm volatile("barrier.cluster.arrive.aligned;" ::: "memory");      \
    asm volatile("barrier.cluster.wait.aligned;"   ::: "memory");      \
} while (0)

// store a tagged 64-bit word into the same smem offset of CTA 'rank'
__device__ __forceinline__ void remote_st_u64(void* lptr, int rank,
                                              unsigned long long val)
{
    unsigned laddr;
    asm("{ .reg .u64 t; cvta.to.shared.u64 t, %1; cvt.u32.u64 %0, t; }"
        : "=r"(laddr) : "l"(lptr));
    unsigned raddr;
    asm volatile("mapa.shared::cluster.u32 %0, %1, %2;"
                 : "=r"(raddr) : "r"(laddr), "r"(rank));
    asm volatile("st.shared::cluster.u64 [%0], %1;"
                 :: "r"(raddr), "l"(val) : "memory");
}

// spin on a local-smem tagged word until its tag (high 32b) matches
__device__ __forceinline__ unsigned poll_mask(
    const volatile unsigned long long* p, unsigned tag)
{
    unsigned long long v = *p;
    while ((unsigned)(v >> 32) != tag) v = *p;
    return (unsigned)v;
}

// XLA logistic: 1/(1+exp(-x)), exp via fp64 rounded to f32 (passing numerics).
__device__ __forceinline__ float sigmoid_ref(float g)
{
    float ef = (float)exp(-(double)g);
    return __fdiv_rn(1.0f, __fadd_rn(1.0f, ef));
}

// ---------------------------------------------------------------
// float2 active-row sum (bit-exact since R7): two independent
// single-accumulator chains in strictly ascending j order; ZROW pads
// add exact +0.0f. 16 independent LDG.64 per batch -> MLP=16/thread.
// ---------------------------------------------------------------
__device__ __forceinline__ float2 mv2(const float* __restrict__ Wb,
                                      const int* __restrict__ lst, int n16)
{
    float2 m = make_float2(0.f, 0.f);
    const int4* l4 = reinterpret_cast<const int4*>(lst);
    const int nb = n16 >> 4;
    for (int k = 0; k < nb; k++) {
        int4 a = l4[k * 4 + 0];
        int4 b = l4[k * 4 + 1];
        int4 c = l4[k * 4 + 2];
        int4 d = l4[k * 4 + 3];
        float2 w0  = *reinterpret_cast<const float2*>(Wb + ((size_t)a.x << 9));
        float2 w1  = *reinterpret_cast<const float2*>(Wb + ((size_t)a.y << 9));
        float2 w2  = *reinterpret_cast<const float2*>(Wb + ((size_t)a.z << 9));
        float2 w3  = *reinterpret_cast<const float2*>(Wb + ((size_t)a.w << 9));
        float2 w4  = *reinterpret_cast<const float2*>(Wb + ((size_t)b.x << 9));
        float2 w5  = *reinterpret_cast<const float2*>(Wb + ((size_t)b.y << 9));
        float2 w6  = *reinterpret_cast<const float2*>(Wb + ((size_t)b.z << 9));
        float2 w7  = *reinterpret_cast<const float2*>(Wb + ((size_t)b.w << 9));
        float2 w8  = *reinterpret_cast<const float2*>(Wb + ((size_t)c.x << 9));
        float2 w9  = *reinterpret_cast<const float2*>(Wb + ((size_t)c.y << 9));
        float2 w10 = *reinterpret_cast<const float2*>(Wb + ((size_t)c.z << 9));
        float2 w11 = *reinterpret_cast<const float2*>(Wb + ((size_t)c.w << 9));
        float2 w12 = *reinterpret_cast<const float2*>(Wb + ((size_t)d.x << 9));
        float2 w13 = *reinterpret_cast<const float2*>(Wb + ((size_t)d.y << 9));
        float2 w14 = *reinterpret_cast<const float2*>(Wb + ((size_t)d.z << 9));
        float2 w15 = *reinterpret_cast<const float2*>(Wb + ((size_t)d.w << 9));
        m.x = __fadd_rn(m.x, w0.x);  m.y = __fadd_rn(m.y, w0.y);
        m.x = __fadd_rn(m.x, w1.x);  m.y = __fadd_rn(m.y, w1.y);
        m.x = __fadd_rn(m.x, w2.x);  m.y = __fadd_rn(m.y, w2.y);
        m.x = __fadd_rn(m.x, w3.x);  m.y = __fadd_rn(m.y, w3.y);
        m.x = __fadd_rn(m.x, w4.x);  m.y = __fadd_rn(m.y, w4.y);
        m.x = __fadd_rn(m.x, w5.x);  m.y = __fadd_rn(m.y, w5.y);
        m.x = __fadd_rn(m.x, w6.x);  m.y = __fadd_rn(m.y, w6.y);
        m.x = __fadd_rn(m.x, w7.x);  m.y = __fadd_rn(m.y, w7.y);
        m.x = __fadd_rn(m.x, w8.x);  m.y = __fadd_rn(m.y, w8.y);
        m.x = __fadd_rn(m.x, w9.x);  m.y = __fadd_rn(m.y, w9.y);
        m.x = __fadd_rn(m.x, w10.x); m.y = __fadd_rn(m.y, w10.y);
        m.x = __fadd_rn(m.x, w11.x); m.y = __fadd_rn(m.y, w11.y);
        m.x = __fadd_rn(m.x, w12.x); m.y = __fadd_rn(m.y, w12.y);
        m.x = __fadd_rn(m.x, w13.x); m.y = __fadd_rn(m.y, w13.y);
        m.x = __fadd_rn(m.x, w14.x); m.y = __fadd_rn(m.y, w14.y);
        m.x = __fadd_rn(m.x, w15.x); m.y = __fadd_rn(m.y, w15.y);
    }
    return m;
}

// local pair index k in [0,128) -> global gate col of pair base 2k
__device__ __forceinline__ int paircol(int k, int rank)
{
    int c = 2 * k;
    return (c < 128) ? (rank * 128 + c) : (256 + rank * 128 + (c - 128));
}

// ---------------------------------------------------------------
// Kernel 2: spiking-LSTM scan, depth-2 pipelined. 64 clusters x 2 CTAs.
// Mask exchange is point-to-point tagged DSMEM stores + local-smem polls:
// NO per-step cluster barrier -> NO per-step L1D flush (weights stay hot).
//   update phase (t): warps 0-3: L0(t); warps 4-7: L1(t-1) (out row t-1)
//   [syncthreads; builds poll tagged masks: m0t tag=t+1, m1t tag=t]
//   matvec phase: Wi1.h0(t) | Wh0.h0(t) | Wh1.h1(t-1) | gx prefetch
// ---------------------------------------------------------------
__global__ void __launch_bounds__(512, 1) __cluster_dims__(2, 1, 1)
recurrent2(const float* __restrict__ bi1,
           const float* __restrict__ bh1,
           float* __restrict__ out)
{
    const int tid  = threadIdx.x;
    const int lane = tid & 31;
    const int warp = tid >> 5;
    const int rank = (int)ctarank();
    const int b    = blockIdx.x >> 1;

    __shared__ float gxs[512];     // double-buffered gx [2][256]
    __shared__ float m0s[256];     // Wh0 . h0(t-1) (precomputed)
    __shared__ float mhs[256];     // Wh1 . h1(t-2->t-1) (precomputed)
    __shared__ float g1s[256];     // (Wi1.h0 + bi1) + bh1 (precomputed)
    __shared__ float c0s[128], c1s[128];
    __shared__ alignas(16) int lst0[WROWS], lst1[WROWS];
    __shared__ unsigned long long m0t[8], m1t[8];   // {tag,mask} words
    __shared__ int n0s, n1s;

    if (tid < 256) m0s[tid] = 0.f;
    if (tid < 128) { c0s[tid] = 0.f; c1s[tid] = 0.f; }
    if (tid < 8)   { m0t[tid] = 0ULL; m1t[tid] = 0ULL; }  // tag 0, mask 0
    if (tid == 0)  { n0s = 0; n1s = 0; }
    if (tid < WROWS) { lst0[tid] = ZROW; lst1[tid] = ZROW; }

    // biases for Wi1 threads (tid<128), float2 per pair
    float2 bi1v = make_float2(0.f, 0.f), bh1v = bi1v;
    if (tid < 128) {
        int g0 = paircol(tid, rank);
        bi1v = *reinterpret_cast<const float2*>(bi1 + g0);
        bh1v = *reinterpret_cast<const float2*>(bh1 + g0);
    }

    const float* gxb = g_gx + (size_t)b * ((size_t)SEQ * GATES);
    const int ubase  = rank * 128;

    // prefetch gx(0) into buffer 0
    if (tid >= 384) {
        int v = tid - 384;
        gxs[v]       = __ldcg(gxb + (ubase + v));
        gxs[128 + v] = __ldcg(gxb + (256 + ubase + v));
    }
    __syncthreads();
    CLUSTER_SYNC();        // startup only: peer smem zeroed before exchanges

    for (int t = 0; t < SEQ; ++t) {
        const int pb = (t & 1) * 256;

        // ---------------- update phase ----------------
        if (tid < 128) {
            // L0(t): gates = gx(t) + Wh0.h0(t-1)
            float g  = __fadd_rn(gxs[pb + tid],       m0s[tid]);
            float ct = __fadd_rn(gxs[pb + 128 + tid], m0s[128 + tid]);
            float f  = sigmoid_ref(g);
            float cc = __fadd_rn(__fmul_rn(f, c0s[tid]),
                                 __fmul_rn(__fsub_rn(1.0f, f), ct));
            c0s[tid] = cc;
            unsigned bal = __ballot_sync(0xffffffffu, cc > 0.f);
            if (lane == 0) {
                int idx = 4 * rank + warp;
                unsigned long long val =
                    ((unsigned long long)(unsigned)(t + 1) << 32) | bal;
                m0t[idx] = val;                       // local
                remote_st_u64(&m0t[idx], rank ^ 1, val);
            }
        } else if (tid < 256 && t > 0) {
            // L1(t-1): gates = ((Wi1.h0+bi1)+bh1) + Wh1.h1(t-2)
            int v = tid - 128;
            float g  = __fadd_rn(g1s[v],       mhs[v]);
            float ct = __fadd_rn(g1s[128 + v], mhs[128 + v]);
            float f  = sigmoid_ref(g);
            float cc = __fadd_rn(__fmul_rn(f, c1s[v]),
                                 __fmul_rn(__fsub_rn(1.0f, f), ct));
            c1s[v] = cc;
            float h = (cc > 0.f) ? 1.f : 0.f;
            out[((size_t)b * SEQ + (t - 1)) * HID + (ubase + v)] = h;
            unsigned bal = __ballot_sync(0xffffffffu, cc > 0.f);
            if (lane == 0) {
                int idx = 4 * rank + (warp - 4);
                unsigned long long val =
                    ((unsigned long long)(unsigned)t << 32) | bal;
                m1t[idx] = val;                       // local
                remote_st_u64(&m1t[idx], rank ^ 1, val);
            }
        }
        __syncthreads();   // local mask words + update results visible CTA-wide

        // ---- builds with inline tagged polls (no cluster barrier) ----
        if (tid < 256) {
            // lst0(t): masks tagged t+1
            int j = tid, pre = 0, tot = 0;
            unsigned mw = 0;
#pragma unroll
            for (int w = 0; w < 8; w++) {
                unsigned mm = poll_mask(&m0t[w], (unsigned)(t + 1));
                tot += __popc(mm);
                if (w < (j >> 5)) pre += __popc(mm);
                else if (w == (j >> 5)) {
                    mw = mm;
                    pre += __popc(mm & ((1u << (j & 31)) - 1u));
                }
            }
            if ((mw >> (j & 31)) & 1u) lst0[pre] = j;
            if (j < 16) lst0[tot + j] = ZROW;
            if (j == 0) n0s = (tot + 15) & ~15;
        } else {
            // lst1(t-1): masks tagged t (tag 0 preseeded = initial h1=0)
            int j = tid - 256, pre = 0, tot = 0;
            unsigned mw = 0;
#pragma unroll
            for (int w = 0; w < 8; w++) {
                unsigned mm = poll_mask(&m1t[w], (unsigned)t);
                tot += __popc(mm);
                if (w < (j >> 5)) pre += __popc(mm);
                else if (w == (j >> 5)) {
                    mw = mm;
                    pre += __popc(mm & ((1u << (j & 31)) - 1u));
                }
            }
            if ((mw >> (j & 31)) & 1u) lst1[pre] = j;
            if (j < 16) lst1[tot + j] = ZROW;
            if (j == 0) n1s = (tot + 15) & ~15;
        }
        __syncthreads();

        // ---------------- matvec phase (all three concurrent) ----------
        if (tid < 128) {
            int g0 = paircol(tid, rank);
            float2 mi = mv2(g_WiT1 + g0, lst0, n0s);
            float2 gi;
            gi.x = __fadd_rn(__fadd_rn(mi.x, bi1v.x), bh1v.x);
            gi.y = __fadd_rn(__fadd_rn(mi.y, bi1v.y), bh1v.y);
            *reinterpret_cast<float2*>(&g1s[2 * tid]) = gi;
        } else if (tid < 256) {
            int k  = tid - 128;
            int g0 = paircol(k, rank);
            float2 m0 = mv2(g_WhT0 + g0, lst0, n0s);
            *reinterpret_cast<float2*>(&m0s[2 * k]) = m0;
        } else if (tid < 384) {
            int k  = tid - 256;
            int g0 = paircol(k, rank);
            float2 mh = mv2(g_WhT1 + g0, lst1, n1s);
            *reinterpret_cast<float2*>(&mhs[2 * k]) = mh;
        } else {
            int tn = t + 1;
            if (tn < SEQ) {
                int v  = tid - 384;
                int nb = (tn & 1) * 256;
                gxs[nb + v]       = __ldcg(gxb + (size_t)tn * GATES + (ubase + v));
                gxs[nb + 128 + v] = __ldcg(gxb + (size_t)tn * GATES + (256 + ubase + v));
            }
        }
        __syncthreads();
    }

    // -------- epilogue: L1 update for step SEQ-1 --------
    if (tid < 128) {
        float g  = __fadd_rn(g1s[tid],       mhs[tid]);
        float ct = __fadd_rn(g1s[128 + tid], mhs[128 + tid]);
        float f  = sigmoid_ref(g);
        float cc = __fadd_rn(__fmul_rn(f, c1s[tid]),
                             __fmul_rn(__fsub_rn(1.0f, f), ct));
        c1s[tid] = cc;
        out[((size_t)b * SEQ + (SEQ - 1)) * HID + (ubase + tid)] =
            (cc > 0.f) ? 1.f : 0.f;
    }
    __syncthreads();

    // finals: h_n (2,B,H) then c_n (2,B,H) after the (B,S,H) output
    if (tid < 128) {
        const size_t HN = (size_t)BATCH * SEQ * HID;
        const size_t CN = HN + (size_t)2 * BATCH * HID;
        const int ui = ubase + tid;
        float cc0 = c0s[tid], cc1 = c1s[tid];
        out[HN + ((size_t)0 * BATCH + b) * HID + ui] = (cc0 > 0.f) ? 1.f : 0.f;
        out[HN + ((size_t)1 * BATCH + b) * HID + ui] = (cc1 > 0.f) ? 1.f : 0.f;
        out[CN + ((size_t)0 * BATCH + b) * HID + ui] = cc0;
        out[CN + ((size_t)1 * BATCH + b) * HID + ui] = cc1;
    }

    // shutdown: no CTA exits while peer DSMEM stores may be in flight
    CLUSTER_SYNC();
}

// ---------------------------------------------------------------
extern "C" void kernel_launch(void* const* d_in, const int* in_sizes, int n_in,
                              void* d_out, int out_size)
{
    const float* x   = (const float*)d_in[0];
    const float* Wi0 = (const float*)d_in[1];
    const float* bi0 = (const float*)d_in[2];
    const float* Wh0 = (const float*)d_in[3];
    const float* bh0 = (const float*)d_in[4];
    const float* Wi1 = (const float*)d_in[5];
    const float* bi1 = (const float*)d_in[6];
    const float* Wh1 = (const float*)d_in[7];
    const float* bh1 = (const float*)d_in[8];
    float* out = (float*)d_out;

    prep_kernel<<<1632, 256>>>(Wh0, Wi1, Wh1);

    dim3 gg(2048, 8);
    gemm_gx_kernel<<<gg, 256>>>(x, Wi0, bi0, bh0);

    recurrent2<<<BATCH * 2, 512>>>(bi1, bh1, out);
}